// round 1
// baseline (speedup 1.0000x reference)
#include <cuda_runtime.h>
#include <cuda_bf16.h>
#include <cstdint>

// Problem constants
#define Bb 64
#define Vv 64
#define Tt 256
#define Ff 64
#define NEG_SLOPE 0.01f

// Scratch: H_agg laid out [t][b][v] so kernel1 writes contiguously per block
// and kernel2 reads 64 contiguous floats per (b,t).
__device__ float g_hagg[(size_t)Tt * Bb * Vv];   // 4 MB

// ---------------------------------------------------------------------------
// Kernel 1: per-t block. adj_t = sigmoid(A_t)*(1-I)+I ; H_agg[t][b][v] =
// sum_w adj_t[v][w] * X[b][w][t].  A read from DRAM exactly once.
// ---------------------------------------------------------------------------
__global__ __launch_bounds__(256) void hagg_kernel(const float* __restrict__ X,
                                                   const float* __restrict__ A) {
    const int t = blockIdx.x;
    __shared__ float sA[Vv][Vv + 1];   // adj_t[v][w], padded vs bank conflicts
    __shared__ float sX[Bb][Vv + 1];   // x[b][w] = X[b][w][t]

    const int tid = threadIdx.x;

    // Load + transform A[t] (4096 contiguous floats)
    const float* At = A + (size_t)t * (Vv * Vv);
#pragma unroll
    for (int k = 0; k < 16; k++) {
        int idx = tid + k * 256;
        int v = idx >> 6, w = idx & 63;
        float a = At[idx];
        float s = (v == w) ? 1.0f : (1.0f / (1.0f + __expf(-a)));
        sA[v][w] = s;
    }
    // Load X[:, :, t]  (stride-T gather)
#pragma unroll
    for (int k = 0; k < 16; k++) {
        int idx = tid + k * 256;
        int b = idx >> 6, w = idx & 63;
        sX[b][w] = X[((size_t)b * Vv + w) * Tt + t];
    }
    __syncthreads();

    // 16x16 thread grid, each thread computes a 4(b) x 4(v) tile
    const int tx = tid & 15;   // v base
    const int ty = tid >> 4;   // b base

    float acc[4][4];
#pragma unroll
    for (int i = 0; i < 4; i++)
#pragma unroll
        for (int j = 0; j < 4; j++) acc[i][j] = 0.0f;

#pragma unroll
    for (int w = 0; w < Vv; w++) {
        float xv[4], av[4];
#pragma unroll
        for (int i = 0; i < 4; i++) xv[i] = sX[ty + 16 * i][w];
#pragma unroll
        for (int j = 0; j < 4; j++) av[j] = sA[tx + 16 * j][w];
#pragma unroll
        for (int i = 0; i < 4; i++)
#pragma unroll
            for (int j = 0; j < 4; j++) acc[i][j] = fmaf(av[j], xv[i], acc[i][j]);
    }

    float* out = g_hagg + (size_t)t * Bb * Vv;
#pragma unroll
    for (int i = 0; i < 4; i++)
#pragma unroll
        for (int j = 0; j < 4; j++)
            out[(ty + 16 * i) * Vv + (tx + 16 * j)] = acc[i][j];
}

// ---------------------------------------------------------------------------
// Kernel 2: per-(b,t) block. out[b,t,v*F+f] = leaky(H_agg[t][b][v] * W[f]).
// 16 KB of coalesced float4 streaming stores per block — pure write roofline.
// ---------------------------------------------------------------------------
__global__ __launch_bounds__(256) void expand_kernel(const float* __restrict__ W,
                                                     float* __restrict__ out) {
    const int t = blockIdx.x;
    const int b = blockIdx.y;

    __shared__ float  sH[Vv];
    __shared__ float4 sW[Ff / 4];

    const int tid = threadIdx.x;
    if (tid < Vv) sH[tid] = g_hagg[((size_t)t * Bb + b) * Vv + tid];
    if (tid < Ff / 4) sW[tid] = reinterpret_cast<const float4*>(W)[tid];
    __syncthreads();

    float4* o = reinterpret_cast<float4*>(out) + ((size_t)b * Tt + t) * (Vv * Ff / 4);

#pragma unroll
    for (int k = 0; k < 4; k++) {
        int q = tid + k * 256;          // float4 index within the (b,t) tile
        float h = sH[q >> 4];           // v = q/16
        float4 w4 = sW[q & 15];         // f4 = q%16
        float4 r;
        r.x = h * w4.x; r.x = (r.x >= 0.0f) ? r.x : NEG_SLOPE * r.x;
        r.y = h * w4.y; r.y = (r.y >= 0.0f) ? r.y : NEG_SLOPE * r.y;
        r.z = h * w4.z; r.z = (r.z >= 0.0f) ? r.z : NEG_SLOPE * r.z;
        r.w = h * w4.w; r.w = (r.w >= 0.0f) ? r.w : NEG_SLOPE * r.w;
        __stcs(&o[q], r);               // streaming store: evict-first in L2
    }
}

extern "C" void kernel_launch(void* const* d_in, const int* in_sizes, int n_in,
                              void* d_out, int out_size) {
    const float* X = (const float*)d_in[0];   // [B, V, T]
    const float* A = (const float*)d_in[1];   // [T, V, V]
    const float* W = (const float*)d_in[2];   // [F, 1]
    float* out = (float*)d_out;               // [B, T, V*F]

    hagg_kernel<<<Tt, 256>>>(X, A);
    dim3 grid2(Tt, Bb);
    expand_kernel<<<grid2, 256>>>(W, out);
}